// round 1
// baseline (speedup 1.0000x reference)
#include <cuda_runtime.h>
#include <math.h>
#include <stdint.h>

// Problem constants
#define NB   32
#define NT   512
#define NC   256
#define ND   1024
#define NH   16
#define NL   6
#define NFF  4096
#define NO   256
#define NQ   8
#define NK   1024
#define NHD  64
#define NTOK (NB*NT)   // 16384

// ---------------- scratch (device globals; no allocation allowed) ----------
__device__ float g_h  [(size_t)NTOK * ND];        // 64 MB  residual stream
__device__ float g_a  [(size_t)NTOK * ND];        // 64 MB  ln out / attn out
__device__ float g_qkv[(size_t)NTOK * 3 * ND];    // 192 MB
__device__ float g_ff [(size_t)NTOK * NFF];       // 256 MB
__device__ float g_last[NB * ND];
__device__ float g_z1  [NB * ND];
__device__ float g_z   [NB * NO];

__device__ __forceinline__ float gelu_exact(float v) {
    return 0.5f * v * (1.0f + erff(v * 0.70710678118654752f));
}

// ---------------------------------------------------------------------------
// Tiled fp32 GEMM: C[M,N] = A[M,K] @ W[K,N] (+ epilogue)
// MODE 0: +bias ; MODE 1: +bias +pos[(row%NT)*N+col] ; MODE 2: gelu(+bias)
// MODE 3: extra[row*N+col] + acc + bias   (residual add)
// Requires M%64==0, N%64==0, K%16==0 (true for all call sites).
// ---------------------------------------------------------------------------
template<int MODE>
__global__ __launch_bounds__(256)
void gemm64(const float* __restrict__ A, const float* __restrict__ W,
            const float* __restrict__ bias, const float* __restrict__ extra,
            float* __restrict__ C, int M, int N, int K)
{
    __shared__ float As[16][64];
    __shared__ float Bs[16][64];
    const int tid = threadIdx.x;
    const int tx  = tid & 15, ty = tid >> 4;
    const int rowBase = blockIdx.y * 64;
    const int colBase = blockIdx.x * 64;

    float acc[4][4];
#pragma unroll
    for (int i = 0; i < 4; i++)
#pragma unroll
        for (int j = 0; j < 4; j++) acc[i][j] = 0.f;

    for (int kt = 0; kt < K; kt += 16) {
#pragma unroll
        for (int l = 0; l < 4; l++) {
            int lin = tid + l * 256;
            int m = lin >> 4, k = lin & 15;
            As[k][m] = A[(size_t)(rowBase + m) * K + kt + k];
        }
#pragma unroll
        for (int l = 0; l < 4; l++) {
            int lin = tid + l * 256;
            int k = lin >> 6, n = lin & 63;
            Bs[k][n] = W[(size_t)(kt + k) * N + colBase + n];
        }
        __syncthreads();
#pragma unroll
        for (int k = 0; k < 16; k++) {
            float4 a4 = *(const float4*)&As[k][ty * 4];
            float4 b4 = *(const float4*)&Bs[k][tx * 4];
            float av[4] = {a4.x, a4.y, a4.z, a4.w};
            float bv[4] = {b4.x, b4.y, b4.z, b4.w};
#pragma unroll
            for (int i = 0; i < 4; i++)
#pragma unroll
                for (int j = 0; j < 4; j++) acc[i][j] += av[i] * bv[j];
        }
        __syncthreads();
    }

#pragma unroll
    for (int i = 0; i < 4; i++) {
        int row = rowBase + ty * 4 + i;
#pragma unroll
        for (int j = 0; j < 4; j++) {
            int col = colBase + tx * 4 + j;
            float v = acc[i][j] + bias[col];
            if (MODE == 1) v += extra[(size_t)(row % NT) * N + col];
            if (MODE == 2) v = gelu_exact(v);
            if (MODE == 3) v += extra[(size_t)row * N + col];
            C[(size_t)row * N + col] = v;
        }
    }
}

// ---------------------------------------------------------------------------
// LayerNorm over D=1024. One block per row (256 threads, one float4 each).
// rowStride lets us LN a strided view (last token of each batch).
// ---------------------------------------------------------------------------
__global__ __launch_bounds__(256)
void ln_kernel(const float* __restrict__ x, const float* __restrict__ g,
               const float* __restrict__ b, float* __restrict__ y,
               size_t rowStride)
{
    __shared__ float red[18];
    const int row = blockIdx.x, tid = threadIdx.x;
    const float* xr = x + (size_t)row * rowStride;
    float4 v = ((const float4*)xr)[tid];
    float s  = v.x + v.y + v.z + v.w;
    float sq = v.x * v.x + v.y * v.y + v.z * v.z + v.w * v.w;
#pragma unroll
    for (int o = 16; o > 0; o >>= 1) {
        s  += __shfl_xor_sync(0xffffffffu, s,  o);
        sq += __shfl_xor_sync(0xffffffffu, sq, o);
    }
    if ((tid & 31) == 0) { red[tid >> 5] = s; red[8 + (tid >> 5)] = sq; }
    __syncthreads();
    if (tid < 32) {
        float ws = (tid < 8) ? red[tid]     : 0.f;
        float wq = (tid < 8) ? red[8 + tid] : 0.f;
#pragma unroll
        for (int o = 4; o > 0; o >>= 1) {
            ws += __shfl_xor_sync(0xffffffffu, ws, o);
            wq += __shfl_xor_sync(0xffffffffu, wq, o);
        }
        if (tid == 0) { red[16] = ws; red[17] = wq; }
    }
    __syncthreads();
    float mean = red[16] * (1.f / ND);
    float var  = red[17] * (1.f / ND) - mean * mean;
    float rstd = rsqrtf(var + 1e-5f);
    float4 gg = ((const float4*)g)[tid];
    float4 bb = ((const float4*)b)[tid];
    float4 o4;
    o4.x = (v.x - mean) * rstd * gg.x + bb.x;
    o4.y = (v.y - mean) * rstd * gg.y + bb.y;
    o4.z = (v.z - mean) * rstd * gg.z + bb.z;
    o4.w = (v.w - mean) * rstd * gg.w + bb.w;
    ((float4*)(y + (size_t)row * ND))[tid] = o4;
}

// ---------------------------------------------------------------------------
// Flash attention, causal. HD=64. Tile: 64 queries x 64 keys.
// grid = (NT/64, NH, NB), 256 threads. Thread t: query row r=t/4,
// 16 interleaved cols c = (t&3) + 4*j  (conflict-free smem with stride 65).
// qkv layout per token: [3*D] = c*D + h*64 + d.
// ---------------------------------------------------------------------------
#define AST 65
#define ATTN_SMEM (4 * 64 * AST * (int)sizeof(float))

__global__ __launch_bounds__(256)
void attn_kernel(const float* __restrict__ qkv, float* __restrict__ o)
{
    extern __shared__ float sm[];
    float* sQ = sm;
    float* sK = sQ + 64 * AST;
    float* sV = sK + 64 * AST;
    float* sP = sV + 64 * AST;

    const int qt = blockIdx.x, h = blockIdx.y, b = blockIdx.z;
    const int tid = threadIdx.x;
    const int r = tid >> 2;       // query row within tile
    const int cg = tid & 3;       // col group
    const float scale = 0.125f;   // 1/sqrt(64)

    // Load Q tile
    for (int l = tid; l < 64 * 64; l += 256) {
        int m = l >> 6, d = l & 63;
        sQ[m * AST + d] =
            qkv[(size_t)(b * NT + qt * 64 + m) * (3 * ND) + h * 64 + d];
    }

    float m_run = -1e30f, l_run = 0.f;
    float accO[16];
#pragma unroll
    for (int j = 0; j < 16; j++) accO[j] = 0.f;

    const int qi = qt * 64 + r;

    for (int kt = 0; kt <= qt; kt++) {
        __syncthreads();
        for (int l = tid; l < 64 * 64; l += 256) {
            int m = l >> 6, d = l & 63;
            size_t base = (size_t)(b * NT + kt * 64 + m) * (3 * ND) + h * 64 + d;
            sK[m * AST + d] = qkv[base + ND];
            sV[m * AST + d] = qkv[base + 2 * ND];
        }
        __syncthreads();

        // scores
        float s[16];
#pragma unroll
        for (int j = 0; j < 16; j++) s[j] = 0.f;
        for (int d = 0; d < 64; d++) {
            float qv = sQ[r * AST + d];
#pragma unroll
            for (int j = 0; j < 16; j++)
                s[j] += qv * sK[(cg + 4 * j) * AST + d];
        }
        float tmax = -1e30f;
#pragma unroll
        for (int j = 0; j < 16; j++) {
            int ki = kt * 64 + cg + 4 * j;
            s[j] = (ki <= qi) ? s[j] * scale : -1e30f;
            tmax = fmaxf(tmax, s[j]);
        }
        tmax = fmaxf(tmax, __shfl_xor_sync(0xffffffffu, tmax, 1));
        tmax = fmaxf(tmax, __shfl_xor_sync(0xffffffffu, tmax, 2));
        float m_new = fmaxf(m_run, tmax);
        float corr = expf(m_run - m_new);
        float lsum = 0.f;
#pragma unroll
        for (int j = 0; j < 16; j++) {
            float p = expf(s[j] - m_new);
            lsum += p;
            sP[r * AST + cg + 4 * j] = p;
        }
        lsum += __shfl_xor_sync(0xffffffffu, lsum, 1);
        lsum += __shfl_xor_sync(0xffffffffu, lsum, 2);
        l_run = l_run * corr + lsum;
        m_run = m_new;
#pragma unroll
        for (int j = 0; j < 16; j++) accO[j] *= corr;
        __syncthreads();

        // P @ V
        for (int c = 0; c < 64; c++) {
            float p = sP[r * AST + c];
#pragma unroll
            for (int j = 0; j < 16; j++)
                accO[j] += p * sV[c * AST + cg + 4 * j];
        }
    }

    float inv = 1.f / l_run;
    size_t token = (size_t)(b * NT + qt * 64 + r);
#pragma unroll
    for (int j = 0; j < 16; j++)
        o[token * ND + h * 64 + cg + 4 * j] = accO[j] * inv;
}

// ---------------------------------------------------------------------------
// Small GEMM for the head: out[32,N] = A[32,K] @ W[K,N] + bias (opt gelu)
// One block per row; row cached in smem.
// ---------------------------------------------------------------------------
__global__ __launch_bounds__(256)
void small_gemm(const float* __restrict__ A, const float* __restrict__ W,
                const float* __restrict__ bias, float* __restrict__ out,
                int K, int N, int doGelu)
{
    __shared__ float sA[ND];
    const int row = blockIdx.x, tid = threadIdx.x;
    for (int i = tid; i < K; i += 256) sA[i] = A[(size_t)row * K + i];
    __syncthreads();
    for (int col = tid; col < N; col += 256) {
        float acc = 0.f;
        for (int k = 0; k < K; k++) acc += sA[k] * W[(size_t)k * N + col];
        acc += bias[col];
        if (doGelu) acc = gelu_exact(acc);
        out[(size_t)row * N + col] = acc;
    }
}

// ---------------------------------------------------------------------------
// Residual VQ: 8 sequential levels. One block per sample row (grid=32).
// dist = ||e||^2 - 2 r.e  (argmin order identical to ref's d; ties -> lowest idx)
// ---------------------------------------------------------------------------
__global__ __launch_bounds__(256)
void rvq_kernel(const float* __restrict__ z, const float* __restrict__ codebooks,
                const float* __restrict__ layer_scales, float* __restrict__ out)
{
    __shared__ float res[NO];
    __shared__ float bestd[256];
    __shared__ int   besti[256];
    const int row = blockIdx.x, tid = threadIdx.x;

    res[tid] = z[(size_t)row * NO + tid];
    float outv = 0.f;

    for (int q = 0; q < NQ; q++) {
        __syncthreads();
        const float* cb = codebooks + (size_t)q * NK * NO;
        float bd = 1e30f; int bi = 0;
        for (int c = tid; c < NK; c += 256) {
            const float* e = cb + (size_t)c * NO;
            float dot = 0.f, nrm = 0.f;
            for (int d = 0; d < NO; d += 4) {
                float4 e4 = *(const float4*)(e + d);
                dot += res[d] * e4.x + res[d + 1] * e4.y
                     + res[d + 2] * e4.z + res[d + 3] * e4.w;
                nrm += e4.x * e4.x + e4.y * e4.y + e4.z * e4.z + e4.w * e4.w;
            }
            float dist = nrm - 2.f * dot;
            if (dist < bd) { bd = dist; bi = c; }
        }
        bestd[tid] = bd; besti[tid] = bi;
        __syncthreads();
        for (int sft = 128; sft > 0; sft >>= 1) {
            if (tid < sft) {
                float od = bestd[tid + sft]; int oi = besti[tid + sft];
                if (od < bestd[tid] || (od == bestd[tid] && oi < besti[tid])) {
                    bestd[tid] = od; besti[tid] = oi;
                }
            }
            __syncthreads();
        }
        int best = besti[0];
        float ls = layer_scales[q];
        float sig = 1.f / (1.f + expf(-ls));
        float ev = cb[(size_t)best * NO + tid];
        outv += sig * ev;
        res[tid] = res[tid] - ev;   // RESIDUAL_SCALE = 1.0
    }
    out[(size_t)row * NO + tid] = outv;
}

// ---------------------------------------------------------------------------
extern "C" void kernel_launch(void* const* d_in, const int* in_sizes, int n_in,
                              void* d_out, int out_size)
{
    const float* x      = (const float*)d_in[0];
    const float* w_in   = (const float*)d_in[1];
    const float* b_in   = (const float*)d_in[2];
    const float* pos    = (const float*)d_in[3];
    const float* ln1_g  = (const float*)d_in[4];
    const float* ln1_b  = (const float*)d_in[5];
    const float* qkv_w  = (const float*)d_in[6];
    const float* qkv_b  = (const float*)d_in[7];
    const float* proj_w = (const float*)d_in[8];
    const float* proj_b = (const float*)d_in[9];
    const float* ln2_g  = (const float*)d_in[10];
    const float* ln2_b  = (const float*)d_in[11];
    const float* ff1_w  = (const float*)d_in[12];
    const float* ff1_b  = (const float*)d_in[13];
    const float* ff2_w  = (const float*)d_in[14];
    const float* ff2_b  = (const float*)d_in[15];
    const float* lnf_g  = (const float*)d_in[16];
    const float* lnf_b  = (const float*)d_in[17];
    const float* out1_w = (const float*)d_in[18];
    const float* out1_b = (const float*)d_in[19];
    const float* out2_w = (const float*)d_in[20];
    const float* out2_b = (const float*)d_in[21];
    const float* codebooks    = (const float*)d_in[22];
    const float* layer_scales = (const float*)d_in[23];

    float *h, *a, *qkv, *ff, *last, *z1, *z;
    cudaGetSymbolAddress((void**)&h,    g_h);
    cudaGetSymbolAddress((void**)&a,    g_a);
    cudaGetSymbolAddress((void**)&qkv,  g_qkv);
    cudaGetSymbolAddress((void**)&ff,   g_ff);
    cudaGetSymbolAddress((void**)&last, g_last);
    cudaGetSymbolAddress((void**)&z1,   g_z1);
    cudaGetSymbolAddress((void**)&z,    g_z);

    cudaFuncSetAttribute(attn_kernel,
                         cudaFuncAttributeMaxDynamicSharedMemorySize, ATTN_SMEM);

    const dim3 thr(256);

    // h = x @ w_in + b_in + pos
    gemm64<1><<<dim3(ND / 64, NTOK / 64), thr>>>(x, w_in, b_in, pos, h,
                                                 NTOK, ND, NC);

    for (int l = 0; l < NL; l++) {
        // a = ln1(h)
        ln_kernel<<<NTOK, thr>>>(h, ln1_g + (size_t)l * ND, ln1_b + (size_t)l * ND,
                                 a, ND);
        // qkv = a @ qkv_w + qkv_b
        gemm64<0><<<dim3(3 * ND / 64, NTOK / 64), thr>>>(
            a, qkv_w + (size_t)l * ND * 3 * ND, qkv_b + (size_t)l * 3 * ND,
            nullptr, qkv, NTOK, 3 * ND, ND);
        // a = attention(qkv)
        attn_kernel<<<dim3(NT / 64, NH, NB), thr, ATTN_SMEM>>>(qkv, a);
        // h = h + a @ proj_w + proj_b
        gemm64<3><<<dim3(ND / 64, NTOK / 64), thr>>>(
            a, proj_w + (size_t)l * ND * ND, proj_b + (size_t)l * ND,
            h, h, NTOK, ND, ND);
        // a = ln2(h)
        ln_kernel<<<NTOK, thr>>>(h, ln2_g + (size_t)l * ND, ln2_b + (size_t)l * ND,
                                 a, ND);
        // ff = gelu(a @ ff1_w + ff1_b)
        gemm64<2><<<dim3(NFF / 64, NTOK / 64), thr>>>(
            a, ff1_w + (size_t)l * ND * NFF, ff1_b + (size_t)l * NFF,
            nullptr, ff, NTOK, NFF, ND);
        // h = h + ff @ ff2_w + ff2_b
        gemm64<3><<<dim3(ND / 64, NTOK / 64), thr>>>(
            ff, ff2_w + (size_t)l * NFF * ND, ff2_b + (size_t)l * ND,
            h, h, NTOK, ND, NFF);
    }

    // last = lnf(h[:, -1, :])  (strided: last token of each batch)
    ln_kernel<<<NB, thr>>>(h + (size_t)(NT - 1) * ND, lnf_g, lnf_b, last,
                           (size_t)NT * ND);
    // z1 = gelu(last @ out1_w + out1_b)
    small_gemm<<<NB, thr>>>(last, out1_w, out1_b, z1, ND, ND, 1);
    // z = z1 @ out2_w + out2_b
    small_gemm<<<NB, thr>>>(z1, out2_w, out2_b, z, ND, NO, 0);
    // RVQ -> d_out
    rvq_kernel<<<NB, thr>>>(z, codebooks, layer_scales, (float*)d_out);
}

// round 4
// speedup vs baseline: 3.3174x; 3.3174x over previous
#include <cuda_runtime.h>
#include <cuda_bf16.h>
#include <math.h>
#include <stdint.h>

// ---------------- problem constants ----------------
#define NB   32
#define NT   512
#define NC   256
#define ND   1024
#define NH   16
#define NL   6
#define NFF  4096
#define NO   256
#define NQ   8
#define NK   1024
#define NTOK (NB*NT)   // 16384

// ---------------- transposed/split weight buffer offsets (elements) --------
#define QKV_SZ   (ND*3*ND)
#define PROJ_SZ  (ND*ND)
#define FF1_SZ   (ND*NFF)
#define FF2_SZ   (NFF*ND)
#define OFF_WIN  0
#define OFF_QKV  (NC*ND)
#define OFF_PROJ (OFF_QKV + 6*QKV_SZ)
#define OFF_FF1  (OFF_PROJ + 6*PROJ_SZ)
#define OFF_FF2  (OFF_FF1 + 6*FF1_SZ)
#define W_TOTAL  (OFF_FF2 + 6*FF2_SZ)

// ---------------- scratch (device globals) ----------------
__device__ float g_h  [(size_t)NTOK * ND];
__device__ float g_qkv[(size_t)NTOK * 3 * ND];
__device__ float g_last[NB * ND];
__device__ float g_z1  [NB * ND];
__device__ float g_z   [NB * NO];

__device__ __nv_bfloat16 g_whi[W_TOTAL];
__device__ __nv_bfloat16 g_wlo[W_TOTAL];
__device__ __nv_bfloat16 g_ahi[(size_t)NTOK * ND];
__device__ __nv_bfloat16 g_alo[(size_t)NTOK * ND];
__device__ __nv_bfloat16 g_ffhi[(size_t)NTOK * NFF];
__device__ __nv_bfloat16 g_fflo[(size_t)NTOK * NFF];
__device__ __nv_bfloat16 g_xhi[(size_t)NTOK * NC];
__device__ __nv_bfloat16 g_xlo[(size_t)NTOK * NC];

__device__ __forceinline__ float gelu_exact(float v) {
    return 0.5f * v * (1.0f + erff(v * 0.70710678118654752f));
}
__device__ __forceinline__ void split_bf16(float v, __nv_bfloat16& h, __nv_bfloat16& l) {
    h = __float2bfloat16(v);
    l = __float2bfloat16(v - __bfloat162float(h));
}

// ---------------- PTX helpers (base sm_103 ISA only) ----------------
__device__ __forceinline__ uint32_t smem_u32(const void* p) {
    uint32_t a;
    asm("{ .reg .u64 t; cvta.to.shared.u64 t, %1; cvt.u32.u64 %0, t; }"
        : "=r"(a) : "l"(p));
    return a;
}
__device__ __forceinline__ void cp16(uint32_t dst, const void* src) {
    asm volatile("cp.async.cg.shared.global [%0], [%1], 16;"
                 :: "r"(dst), "l"(src) : "memory");
}
#define CP_COMMIT() asm volatile("cp.async.commit_group;" ::: "memory")
#define CP_WAIT1()  asm volatile("cp.async.wait_group 1;" ::: "memory")
#define CP_WAIT0()  asm volatile("cp.async.wait_group 0;" ::: "memory")

__device__ __forceinline__ void ldsm_x4(uint32_t* r, uint32_t addr) {
    asm volatile("ldmatrix.sync.aligned.m8n8.x4.shared.b16 {%0,%1,%2,%3}, [%4];"
                 : "=r"(r[0]), "=r"(r[1]), "=r"(r[2]), "=r"(r[3]) : "r"(addr));
}
__device__ __forceinline__ void mma_bf16(float* d, const uint32_t* a, const uint32_t* b) {
    asm volatile("mma.sync.aligned.m16n8k16.row.col.f32.bf16.bf16.f32 "
                 "{%0,%1,%2,%3}, {%4,%5,%6,%7}, {%8,%9}, {%0,%1,%2,%3};"
                 : "+f"(d[0]), "+f"(d[1]), "+f"(d[2]), "+f"(d[3])
                 : "r"(a[0]), "r"(a[1]), "r"(a[2]), "r"(a[3]),
                   "r"(b[0]), "r"(b[1]));
}

// ---------------------------------------------------------------------------
// HMMA split-bf16 GEMM. C[M,N] = A[M,K] @ W[K,N].
// A given as hi/lo bf16 [M,K]; W pre-transposed+split as Bhi/Blo [N,K].
// [N,K] row-major IS col-major B => B fragments via NON-trans ldmatrix of
// n-rows (consecutive-k contiguous), matching mma row.col's B layout.
// Acc += Ahi*Bhi + Ahi*Blo + Alo*Bhi (3-pass Markidis split, fp32 accum).
// Block tile 128x128, BK=32, 256 threads (8 warps, 2Mx4N, warp tile 64x32).
// SMEM rows: 32 bf16 = 64B data + 16B pad = 80B stride.
// MODE 0: C=acc+bias (fp32)    MODE 1: +pos[(row%NT)*N+col]
// MODE 2: gelu(acc+bias) -> Chi/Clo bf16   MODE 3: +extra (residual)
// ---------------------------------------------------------------------------
#define MTILE_B   10240              // 128 rows * 80B
#define STAGE_B   (4*MTILE_B)        // Ahi,Alo,Bhi,Blo
#define GSMEM     (2*STAGE_B)        // 81920

__device__ __forceinline__ void load_stage(
    uint32_t sb, int c, int tid, int rowBase, int colBase, int K,
    const __nv_bfloat16* __restrict__ Ahi, const __nv_bfloat16* __restrict__ Alo,
    const __nv_bfloat16* __restrict__ Bhi, const __nv_bfloat16* __restrict__ Blo)
{
    size_t koff = (size_t)c * 32;
#pragma unroll
    for (int i = 0; i < 2; i++) {
        int lin = tid + (i << 8);
        int r = lin >> 2, q = lin & 3;
        uint32_t so = (uint32_t)(r * 80 + q * 16);
        size_t srcA = (size_t)(rowBase + r) * K + koff + q * 8;
        size_t srcB = (size_t)(colBase + r) * K + koff + q * 8;
        cp16(sb + so,               Ahi + srcA);
        cp16(sb + MTILE_B + so,     Alo + srcA);
        cp16(sb + 2 * MTILE_B + so, Bhi + srcB);
        cp16(sb + 3 * MTILE_B + so, Blo + srcB);
    }
    CP_COMMIT();
}

template<int MODE>
__global__ __launch_bounds__(256)
void gemm_mma(const __nv_bfloat16* __restrict__ Ahi, const __nv_bfloat16* __restrict__ Alo,
              const __nv_bfloat16* __restrict__ Bhi, const __nv_bfloat16* __restrict__ Blo,
              const float* __restrict__ bias, const float* __restrict__ extra,
              float* __restrict__ Cf, __nv_bfloat16* __restrict__ Chi,
              __nv_bfloat16* __restrict__ Clo, int M, int N, int K)
{
    extern __shared__ __align__(1024) unsigned char dynsmem[];
    uint32_t sbase = smem_u32(dynsmem);
    const int tid = threadIdx.x;
    const int lane = tid & 31;
    const int warp = tid >> 5;
    const int warpM = warp & 1;        // 2 warps in M
    const int warpN = warp >> 1;       // 4 warps in N
    const int rowBase = blockIdx.y * 128;
    const int colBase = blockIdx.x * 128;
    const int nc = K >> 5;

    float acc[4][4][4];
#pragma unroll
    for (int mt = 0; mt < 4; mt++)
#pragma unroll
        for (int nt = 0; nt < 4; nt++)
#pragma unroll
            for (int e = 0; e < 4; e++) acc[mt][nt][e] = 0.f;

    load_stage(sbase, 0, tid, rowBase, colBase, K, Ahi, Alo, Bhi, Blo);
    load_stage(sbase + STAGE_B, 1, tid, rowBase, colBase, K, Ahi, Alo, Bhi, Blo);

    // per-lane ldmatrix address components
    // A (non-trans): lanes 0-15 -> rows 0-15 k-offset 0; lanes 16-31 -> rows 0-15 k+8
    const int aRow = warpM * 64 + (lane & 15);          // + mt*16
    const uint32_t aColOff = (uint32_t)((lane >> 4) * 16);
    // B (non-trans, [N,K] storage): lanes 0-7 -> n 0-7 @k0; 8-15 -> n 0-7 @k8;
    // 16-23 -> n 8-15 @k0; 24-31 -> n 8-15 @k8   (per 16-n group, + ng*16)
    const int bRow = warpN * 32 + ((lane >> 4) & 1) * 8 + (lane & 7);  // + ng*16
    const uint32_t bColOff = (uint32_t)(((lane >> 3) & 1) * 16);

    for (int c = 0; c < nc; c++) {
        if (c + 1 < nc) { CP_WAIT1(); } else { CP_WAIT0(); }
        __syncthreads();
        uint32_t sA = sbase + (uint32_t)(c & 1) * STAGE_B;
        uint32_t sB = sA + 2 * MTILE_B;

#pragma unroll
        for (int kk = 0; kk < 2; kk++) {
            uint32_t kb = (uint32_t)(kk * 32);
            uint32_t ah[4][4], al[4][4];
#pragma unroll
            for (int mt = 0; mt < 4; mt++) {
                uint32_t addr = sA + (uint32_t)((aRow + mt * 16) * 80) + kb + aColOff;
                ldsm_x4(ah[mt], addr);
                ldsm_x4(al[mt], addr + MTILE_B);
            }
            uint32_t bh[4][2], bl[4][2];
#pragma unroll
            for (int ng = 0; ng < 2; ng++) {
                uint32_t r4[4];
                uint32_t addr = sB + (uint32_t)((bRow + ng * 16) * 80) + kb + bColOff;
                ldsm_x4(r4, addr);
                bh[ng*2][0] = r4[0]; bh[ng*2][1] = r4[1];
                bh[ng*2+1][0] = r4[2]; bh[ng*2+1][1] = r4[3];
                ldsm_x4(r4, addr + MTILE_B);
                bl[ng*2][0] = r4[0]; bl[ng*2][1] = r4[1];
                bl[ng*2+1][0] = r4[2]; bl[ng*2+1][1] = r4[3];
            }
#pragma unroll
            for (int mt = 0; mt < 4; mt++)
#pragma unroll
                for (int nt = 0; nt < 4; nt++) {
                    mma_bf16(acc[mt][nt], ah[mt], bh[nt]);
                    mma_bf16(acc[mt][nt], ah[mt], bl[nt]);
                    mma_bf16(acc[mt][nt], al[mt], bh[nt]);
                }
        }
        __syncthreads();
        if (c + 2 < nc)
            load_stage(sbase + (uint32_t)(c & 1) * STAGE_B, c + 2, tid,
                       rowBase, colBase, K, Ahi, Alo, Bhi, Blo);
    }

    // epilogue: frag (mt,nt): rows r0=(lane>>2)+{0,8}, cols (lane&3)*2 + {0,1}
#pragma unroll
    for (int mt = 0; mt < 4; mt++) {
        int row0 = rowBase + warpM * 64 + mt * 16 + (lane >> 2);
#pragma unroll
        for (int nt = 0; nt < 4; nt++) {
            int col = colBase + warpN * 32 + nt * 8 + (lane & 3) * 2;
            float b0 = bias[col], b1 = bias[col + 1];
#pragma unroll
            for (int half = 0; half < 2; half++) {
                int row = row0 + half * 8;
                float v0 = acc[mt][nt][half * 2 + 0] + b0;
                float v1 = acc[mt][nt][half * 2 + 1] + b1;
                if (MODE == 1) {
                    size_t pr = (size_t)(row & (NT - 1)) * N + col;
                    v0 += extra[pr]; v1 += extra[pr + 1];
                }
                if (MODE == 3) {
                    size_t pr = (size_t)row * N + col;
                    v0 += extra[pr]; v1 += extra[pr + 1];
                }
                if (MODE == 2) {
                    v0 = gelu_exact(v0); v1 = gelu_exact(v1);
                    __nv_bfloat16 h0, l0, h1, l1;
                    split_bf16(v0, h0, l0); split_bf16(v1, h1, l1);
                    size_t o = (size_t)row * N + col;
                    *(__nv_bfloat162*)(Chi + o) = __nv_bfloat162(h0, h1);
                    *(__nv_bfloat162*)(Clo + o) = __nv_bfloat162(l0, l1);
                } else {
                    size_t o = (size_t)row * N + col;
                    Cf[o] = v0; Cf[o + 1] = v1;
                }
            }
        }
    }
}

// ---------------------------------------------------------------------------
// weight transpose + split: W[K,N] fp32 -> oh/ol [N,K] bf16
// ---------------------------------------------------------------------------
__global__ __launch_bounds__(256)
void tsplit(const float* __restrict__ W, __nv_bfloat16* __restrict__ oh,
            __nv_bfloat16* __restrict__ ol, int K, int N)
{
    __shared__ float t[32][33];
    const int tx = threadIdx.x, ty = threadIdx.y;
    const int n0 = blockIdx.x * 32, k0 = blockIdx.y * 32;
#pragma unroll
    for (int i = 0; i < 4; i++)
        t[ty + 8 * i][tx] = W[(size_t)(k0 + ty + 8 * i) * N + n0 + tx];
    __syncthreads();
#pragma unroll
    for (int i = 0; i < 4; i++) {
        float v = t[tx][ty + 8 * i];
        size_t o = (size_t)(n0 + ty + 8 * i) * K + k0 + tx;
        __nv_bfloat16 h, l; split_bf16(v, h, l);
        oh[o] = h; ol[o] = l;
    }
}

__global__ __launch_bounds__(256)
void xsplit(const float* __restrict__ x, __nv_bfloat16* __restrict__ xh,
            __nv_bfloat16* __restrict__ xl, int n)
{
    int i = blockIdx.x * 256 + threadIdx.x;
    if (i < n) {
        __nv_bfloat16 h, l; split_bf16(x[i], h, l);
        xh[i] = h; xl[i] = l;
    }
}

// ---------------------------------------------------------------------------
// LayerNorm over D=1024. OUT=0: fp32; OUT=1: bf16 hi/lo split.
// ---------------------------------------------------------------------------
template<int OUT>
__global__ __launch_bounds__(256)
void ln_kernel(const float* __restrict__ x, const float* __restrict__ g,
               const float* __restrict__ b, float* __restrict__ yf,
               __nv_bfloat16* __restrict__ yh, __nv_bfloat16* __restrict__ yl,
               size_t rowStride)
{
    __shared__ float red[18];
    const int row = blockIdx.x, tid = threadIdx.x;
    const float* xr = x + (size_t)row * rowStride;
    float4 v = ((const float4*)xr)[tid];
    float s  = v.x + v.y + v.z + v.w;
    float sq = v.x * v.x + v.y * v.y + v.z * v.z + v.w * v.w;
#pragma unroll
    for (int o = 16; o > 0; o >>= 1) {
        s  += __shfl_xor_sync(0xffffffffu, s,  o);
        sq += __shfl_xor_sync(0xffffffffu, sq, o);
    }
    if ((tid & 31) == 0) { red[tid >> 5] = s; red[8 + (tid >> 5)] = sq; }
    __syncthreads();
    if (tid < 32) {
        float ws = (tid < 8) ? red[tid]     : 0.f;
        float wq = (tid < 8) ? red[8 + tid] : 0.f;
#pragma unroll
        for (int o = 4; o > 0; o >>= 1) {
            ws += __shfl_xor_sync(0xffffffffu, ws, o);
            wq += __shfl_xor_sync(0xffffffffu, wq, o);
        }
        if (tid == 0) { red[16] = ws; red[17] = wq; }
    }
    __syncthreads();
    float mean = red[16] * (1.f / ND);
    float var  = red[17] * (1.f / ND) - mean * mean;
    float rstd = rsqrtf(var + 1e-5f);
    float4 gg = ((const float4*)g)[tid];
    float4 bb = ((const float4*)b)[tid];
    float o0 = (v.x - mean) * rstd * gg.x + bb.x;
    float o1 = (v.y - mean) * rstd * gg.y + bb.y;
    float o2 = (v.z - mean) * rstd * gg.z + bb.z;
    float o3 = (v.w - mean) * rstd * gg.w + bb.w;
    if (OUT == 0) {
        float4 o4 = {o0, o1, o2, o3};
        ((float4*)(yf + (size_t)row * ND))[tid] = o4;
    } else {
        size_t base = (size_t)row * ND + tid * 4;
        __nv_bfloat16 h, l;
        split_bf16(o0, h, l); yh[base+0] = h; yl[base+0] = l;
        split_bf16(o1, h, l); yh[base+1] = h; yl[base+1] = l;
        split_bf16(o2, h, l); yh[base+2] = h; yl[base+2] = l;
        split_bf16(o3, h, l); yh[base+3] = h; yl[base+3] = l;
    }
}

// ---------------------------------------------------------------------------
// Flash attention (fp32 SIMT), causal, HD=64. Writes bf16 hi/lo output.
// ---------------------------------------------------------------------------
#define AST 65
#define ATTN_SMEM (4 * 64 * AST * (int)sizeof(float))

__global__ __launch_bounds__(256)
void attn_kernel(const float* __restrict__ qkv,
                 __nv_bfloat16* __restrict__ oh, __nv_bfloat16* __restrict__ ol)
{
    extern __shared__ __align__(1024) unsigned char dynsmem[];
    float* sm = (float*)dynsmem;
    float* sQ = sm;
    float* sK = sQ + 64 * AST;
    float* sV = sK + 64 * AST;
    float* sP = sV + 64 * AST;

    const int qt = blockIdx.x, h = blockIdx.y, b = blockIdx.z;
    const int tid = threadIdx.x;
    const int r = tid >> 2;
    const int cg = tid & 3;
    const float scale = 0.125f;

    for (int l = tid; l < 64 * 64; l += 256) {
        int m = l >> 6, d = l & 63;
        sQ[m * AST + d] =
            qkv[(size_t)(b * NT + qt * 64 + m) * (3 * ND) + h * 64 + d];
    }

    float m_run = -1e30f, l_run = 0.f;
    float accO[16];
#pragma unroll
    for (int j = 0; j < 16; j++) accO[j] = 0.f;
    const int qi = qt * 64 + r;

    for (int kt = 0; kt <= qt; kt++) {
        __syncthreads();
        for (int l = tid; l < 64 * 64; l += 256) {
            int m = l >> 6, d = l & 63;
            size_t base = (size_t)(b * NT + kt * 64 + m) * (3 * ND) + h * 64 + d;
            sK[m * AST + d] = qkv[base + ND];
            sV[m * AST + d] = qkv[base + 2 * ND];
        }
        __syncthreads();

        float s[16];
#pragma unroll
        for (int j = 0; j < 16; j++) s[j] = 0.f;
        for (int d = 0; d < 64; d++) {
            float qv = sQ[r * AST + d];
#pragma unroll
            for (int j = 0; j < 16; j++)
                s[j] += qv * sK[(cg + 4 * j) * AST + d];
        }
        float tmax = -1e30f;
#pragma unroll
        for (int j = 0; j < 16; j++) {
            int ki = kt * 64 + cg + 4 * j;
            s[j] = (ki <= qi) ? s[j] * scale : -1e30f;
            tmax = fmaxf(tmax, s[j]);
        }
        tmax = fmaxf(tmax, __shfl_xor_sync(0xffffffffu, tmax, 1));
        tmax = fmaxf(tmax, __shfl_xor_sync(0xffffffffu, tmax, 2));
        float m_new = fmaxf(m_run, tmax);
        float corr = expf(m_run - m_new);
        float lsum = 0.f;
#pragma unroll
        for (int j = 0; j < 16; j++) {
            float p = expf(s[j] - m_new);
            lsum += p;
            sP[r * AST + cg + 4 * j] = p;
        }
        lsum += __shfl_xor_sync(0xffffffffu, lsum, 1);
        lsum += __shfl_xor_sync(0xffffffffu, lsum, 2);
        l_run = l_run * corr + lsum;
        m_run = m_new;
#pragma unroll
        for (int j = 0; j < 16; j++) accO[j] *= corr;
        __syncthreads();

        for (int c = 0; c < 64; c++) {
            float p = sP[r * AST + c];
#pragma unroll
            for (int j = 0; j < 16; j++)
                accO[j] += p * sV[c * AST + cg + 4 * j];
        }
    }

    float inv = 1.f / l_run;
    size_t token = (size_t)(b * NT + qt * 64 + r);
#pragma unroll
    for (int j = 0; j < 16; j++) {
        float v = accO[j] * inv;
        __nv_bfloat16 hh, ll; split_bf16(v, hh, ll);
        size_t o = token * ND + h * 64 + cg + 4 * j;
        oh[o] = hh; ol[o] = ll;
    }
}

// ---------------------------------------------------------------------------
// Head small GEMMs (tiny) + RVQ
// ---------------------------------------------------------------------------
__global__ __launch_bounds__(256)
void small_gemm(const float* __restrict__ A, const float* __restrict__ W,
                const float* __restrict__ bias, float* __restrict__ out,
                int K, int N, int doGelu)
{
    __shared__ float sA[ND];
    const int row = blockIdx.x, tid = threadIdx.x;
    for (int i = tid; i < K; i += 256) sA[i] = A[(size_t)row * K + i];
    __syncthreads();
    for (int col = tid; col < N; col += 256) {
        float acc = 0.f;
        for (int k = 0; k < K; k++) acc += sA[k] * W[(size_t)k * N + col];
        acc += bias[col];
        if (doGelu) acc = gelu_exact(acc);
        out[(size_t)row * N + col] = acc;
    }
}

__global__ __launch_bounds__(256)
void rvq_kernel(const float* __restrict__ z, const float* __restrict__ codebooks,
                const float* __restrict__ layer_scales, float* __restrict__ out)
{
    __shared__ float res[NO];
    __shared__ float bestd[256];
    __shared__ int   besti[256];
    const int row = blockIdx.x, tid = threadIdx.x;

    res[tid] = z[(size_t)row * NO + tid];
    float outv = 0.f;

    for (int q = 0; q < NQ; q++) {
        __syncthreads();
        const float* cb = codebooks + (size_t)q * NK * NO;
        float bd = 1e30f; int bi = 0;
        for (int c = tid; c < NK; c += 256) {
            const float* e = cb + (size_t)c * NO;
            float dot = 0.f, nrm = 0.f;
            for (int d = 0; d < NO; d += 4) {
                float4 e4 = *(const float4*)(e + d);
                dot += res[d] * e4.x + res[d + 1] * e4.y
                     + res[d + 2] * e4.z + res[d + 3] * e4.w;
                nrm += e4.x * e4.x + e4.y * e4.y + e4.z * e4.z + e4.w * e4.w;
            }
            float dist = nrm - 2.f * dot;
            if (dist < bd) { bd = dist; bi = c; }
        }
        bestd[tid] = bd; besti[tid] = bi;
        __syncthreads();
        for (int sft = 128; sft > 0; sft >>= 1) {
            if (tid < sft) {
                float od = bestd[tid + sft]; int oi = besti[tid + sft];
                if (od < bestd[tid] || (od == bestd[tid] && oi < besti[tid])) {
                    bestd[tid] = od; besti[tid] = oi;
                }
            }
            __syncthreads();
        }
        int best = besti[0];
        float sig = 1.f / (1.f + expf(-layer_scales[q]));
        float ev = cb[(size_t)best * NO + tid];
        outv += sig * ev;
        res[tid] = res[tid] - ev;
    }
    out[(size_t)row * NO + tid] = outv;
}

// ---------------------------------------------------------------------------
extern "C" void kernel_launch(void* const* d_in, const int* in_sizes, int n_in,
                              void* d_out, int out_size)
{
    const float* x      = (const float*)d_in[0];
    const float* w_in   = (const float*)d_in[1];
    const float* b_in   = (const float*)d_in[2];
    const float* pos    = (const float*)d_in[3];
    const float* ln1_g  = (const float*)d_in[4];
    const float* ln1_b  = (const float*)d_in[5];
    const float* qkv_w  = (const float*)d_in[6];
    const float* qkv_b  = (const float*)d_in[7];
    const float* proj_w = (const float*)d_in[8];
    const float* proj_b = (const float*)d_in[9];
    const float* ln2_g  = (const float*)d_in[10];
    const float* ln2_b  = (const float*)d_in[11];
    const float* ff1_w  = (const float*)d_in[12];
    const float* ff1_b  = (const float*)d_in[13];
    const float* ff2_w  = (const float*)d_in[14];
    const float* ff2_b  = (const float*)d_in[15];
    const float* lnf_g  = (const float*)d_in[16];
    const float* lnf_b  = (const float*)d_in[17];
    const float* out1_w = (const float*)d_in[18];
    const float* out1_b = (const float*)d_in[19];
    const float* out2_w = (const float*)d_in[20];
    const float* out2_b = (const float*)d_in[21];
    const float* codebooks    = (const float*)d_in[22];
    const float* layer_scales = (const float*)d_in[23];

    float *h, *qkv, *last, *z1, *z;
    __nv_bfloat16 *whi, *wlo, *ahi, *alo, *ffhi, *fflo, *xhi, *xlo;
    cudaGetSymbolAddress((void**)&h,    g_h);
    cudaGetSymbolAddress((void**)&qkv,  g_qkv);
    cudaGetSymbolAddress((void**)&last, g_last);
    cudaGetSymbolAddress((void**)&z1,   g_z1);
    cudaGetSymbolAddress((void**)&z,    g_z);
    cudaGetSymbolAddress((void**)&whi,  g_whi);
    cudaGetSymbolAddress((void**)&wlo,  g_wlo);
    cudaGetSymbolAddress((void**)&ahi,  g_ahi);
    cudaGetSymbolAddress((void**)&alo,  g_alo);
    cudaGetSymbolAddress((void**)&ffhi, g_ffhi);
    cudaGetSymbolAddress((void**)&fflo, g_fflo);
    cudaGetSymbolAddress((void**)&xhi,  g_xhi);
    cudaGetSymbolAddress((void**)&xlo,  g_xlo);

    cudaFuncSetAttribute(attn_kernel,
                         cudaFuncAttributeMaxDynamicSharedMemorySize, ATTN_SMEM);
    cudaFuncSetAttribute(gemm_mma<0>, cudaFuncAttributeMaxDynamicSharedMemorySize, GSMEM);
    cudaFuncSetAttribute(gemm_mma<1>, cudaFuncAttributeMaxDynamicSharedMemorySize, GSMEM);
    cudaFuncSetAttribute(gemm_mma<2>, cudaFuncAttributeMaxDynamicSharedMemorySize, GSMEM);
    cudaFuncSetAttribute(gemm_mma<3>, cudaFuncAttributeMaxDynamicSharedMemorySize, GSMEM);

    const dim3 thr(256);
    const dim3 tthr(32, 8);

    // ---- input + weight conversions ----
    xsplit<<<(NTOK * NC + 255) / 256, thr>>>(x, xhi, xlo, NTOK * NC);
    tsplit<<<dim3(ND/32, NC/32), tthr>>>(w_in, whi + OFF_WIN, wlo + OFF_WIN, NC, ND);
    for (int l = 0; l < NL; l++) {
        tsplit<<<dim3(3*ND/32, ND/32), tthr>>>(qkv_w + (size_t)l*QKV_SZ,
            whi + OFF_QKV + (size_t)l*QKV_SZ, wlo + OFF_QKV + (size_t)l*QKV_SZ, ND, 3*ND);
        tsplit<<<dim3(ND/32, ND/32), tthr>>>(proj_w + (size_t)l*PROJ_SZ,
            whi + OFF_PROJ + (size_t)l*PROJ_SZ, wlo + OFF_PROJ + (size_t)l*PROJ_SZ, ND, ND);
        tsplit<<<dim3(NFF/32, ND/32), tthr>>>(ff1_w + (size_t)l*FF1_SZ,
            whi + OFF_FF1 + (size_t)l*FF1_SZ, wlo + OFF_FF1 + (size_t)l*FF1_SZ, ND, NFF);
        tsplit<<<dim3(ND/32, NFF/32), tthr>>>(ff2_w + (size_t)l*FF2_SZ,
            whi + OFF_FF2 + (size_t)l*FF2_SZ, wlo + OFF_FF2 + (size_t)l*FF2_SZ, NFF, ND);
    }

    // ---- h = x @ w_in + b_in + pos ----
    gemm_mma<1><<<dim3(ND/128, NTOK/128), thr, GSMEM>>>(
        xhi, xlo, whi + OFF_WIN, wlo + OFF_WIN, b_in, pos,
        h, nullptr, nullptr, NTOK, ND, NC);

    for (int l = 0; l < NL; l++) {
        ln_kernel<1><<<NTOK, thr>>>(h, ln1_g + (size_t)l*ND, ln1_b + (size_t)l*ND,
                                    nullptr, ahi, alo, ND);
        gemm_mma<0><<<dim3(3*ND/128, NTOK/128), thr, GSMEM>>>(
            ahi, alo, whi + OFF_QKV + (size_t)l*QKV_SZ, wlo + OFF_QKV + (size_t)l*QKV_SZ,
            qkv_b + (size_t)l*3*ND, nullptr, qkv, nullptr, nullptr, NTOK, 3*ND, ND);
        attn_kernel<<<dim3(NT/64, NH, NB), thr, ATTN_SMEM>>>(qkv, ahi, alo);
        gemm_mma<3><<<dim3(ND/128, NTOK/128), thr, GSMEM>>>(
            ahi, alo, whi + OFF_PROJ + (size_t)l*PROJ_SZ, wlo + OFF_PROJ + (size_t)l*PROJ_SZ,
            proj_b + (size_t)l*ND, h, h, nullptr, nullptr, NTOK, ND, ND);
        ln_kernel<1><<<NTOK, thr>>>(h, ln2_g + (size_t)l*ND, ln2_b + (size_t)l*ND,
                                    nullptr, ahi, alo, ND);
        gemm_mma<2><<<dim3(NFF/128, NTOK/128), thr, GSMEM>>>(
            ahi, alo, whi + OFF_FF1 + (size_t)l*FF1_SZ, wlo + OFF_FF1 + (size_t)l*FF1_SZ,
            ff1_b + (size_t)l*NFF, nullptr, nullptr, ffhi, fflo, NTOK, NFF, ND);
        gemm_mma<3><<<dim3(ND/128, NTOK/128), thr, GSMEM>>>(
            ffhi, fflo, whi + OFF_FF2 + (size_t)l*FF2_SZ, wlo + OFF_FF2 + (size_t)l*FF2_SZ,
            ff2_b + (size_t)l*ND, h, h, nullptr, nullptr, NTOK, ND, NFF);
    }

    // ---- head ----
    ln_kernel<0><<<NB, thr>>>(h + (size_t)(NT - 1) * ND, lnf_g, lnf_b,
                              last, nullptr, nullptr, (size_t)NT * ND);
    small_gemm<<<NB, thr>>>(last, out1_w, out1_b, z1, ND, ND, 1);
    small_gemm<<<NB, thr>>>(z1, out2_w, out2_b, z, ND, NO, 0);
    rvq_kernel<<<NB, thr>>>(z, codebooks, layer_scales, (float*)d_out);
}